// round 10
// baseline (speedup 1.0000x reference)
#include <cuda_runtime.h>
#include <cuda_bf16.h>
#include <stdint.h>

#define TTYPES   4
#define D_OUT    128
#define FIN      132
#define HID      512
#define MROWS    128
#define NTHREADS 512
#define BUCKET_CAP 262144

#define TW        68            // X/H row stride in words (136 bf16 = 128+8 pad)
#define XH_B      34816         // one X or H buffer (hi or lo)

#define WHALF_ROWW 36           // W half-tile row stride in words (72 bf16)
#define WHALF_ELEM 9216         // 128 * 72 bf16
#define WHALF_B    18432
#define WBUF_B     36864        // hi + lo

// ---------------- device scratch (static: allocation-free) ----------------
__device__ __nv_bfloat16 g_w1t_hi[4 * 2 * WHALF_ELEM];
__device__ __nv_bfloat16 g_w1t_lo[4 * 2 * WHALF_ELEM];
__device__ __nv_bfloat16 g_w2t_hi[16 * 2 * WHALF_ELEM];
__device__ __nv_bfloat16 g_w2t_lo[16 * 2 * WHALF_ELEM];
__device__ int g_counts[TTYPES];
__device__ int g_idx[TTYPES * BUCKET_CAP];

// ---------------- smem layout (bytes) ----------------
#define SM_GIDX  0
#define SM_X_HI  512
#define SM_X_LO  (SM_X_HI + XH_B)
#define SM_W0    (SM_X_LO + XH_B)
#define SM_W1    (SM_W0 + WBUF_B)
#define SM_H_HI  (SM_W1 + WBUF_B)
#define SM_H_LO  (SM_H_HI + XH_B)
#define SM_TOTAL (SM_H_LO + XH_B)        // 213504 B < 227 KB cap

// ---------------- helpers ----------------
__device__ __forceinline__ void mma_bf16(float* c, const uint32_t* a, const uint32_t* b) {
    asm volatile(
        "mma.sync.aligned.m16n8k16.row.col.f32.bf16.bf16.f32 "
        "{%0,%1,%2,%3}, {%4,%5,%6,%7}, {%8,%9}, {%0,%1,%2,%3};"
        : "+f"(c[0]), "+f"(c[1]), "+f"(c[2]), "+f"(c[3])
        : "r"(a[0]), "r"(a[1]), "r"(a[2]), "r"(a[3]), "r"(b[0]), "r"(b[1]));
}
__device__ __forceinline__ uint32_t smem_u32(const void* p) {
    uint32_t a;
    asm("{ .reg .u64 t; cvta.to.shared.u64 t, %1; cvt.u32.u64 %0, t; }"
        : "=r"(a) : "l"(p));
    return a;
}
__device__ __forceinline__ void cpa16(uint32_t s, const void* g) {
    asm volatile("cp.async.cg.shared.global [%0], [%1], 16;" :: "r"(s), "l"(g));
}
#define CPA_COMMIT() asm volatile("cp.async.commit_group;" ::: "memory")
#define CPA_WAIT(n)  asm volatile("cp.async.wait_group %0;" :: "n"(n) : "memory")

__device__ __forceinline__ void split_bf16(float v, unsigned short& h, unsigned short& l) {
    __nv_bfloat16 hb = __float2bfloat16(v);
    h = __bfloat16_as_ushort(hb);
    l = __bfloat16_as_ushort(__float2bfloat16(v - __bfloat162float(hb)));
}
__device__ __forceinline__ void pack2(float a, float b, uint32_t& hi, uint32_t& lo) {
    unsigned short ha, la, hb, lb;
    split_bf16(a, ha, la); split_bf16(b, hb, lb);
    hi = (uint32_t)ha | ((uint32_t)hb << 16);
    lo = (uint32_t)la | ((uint32_t)lb << 16);
}

// ---------------- kernel 0 / 1: counters + bucketing ----------------
__global__ void zero_kernel() {
    if (threadIdx.x < TTYPES) g_counts[threadIdx.x] = 0;
}
__global__ void bucket_kernel(const float* __restrict__ nf, int ntot) {
    int i = blockIdx.x * blockDim.x + threadIdx.x;
    bool v = i < ntot;
    int ty = 0;
    if (v) {
        float4 f = *(const float4*)(nf + (size_t)i * FIN);
        float m = f.x;
        if (f.y > m) { m = f.y; ty = 1; }
        if (f.z > m) { m = f.z; ty = 2; }
        if (f.w > m) { m = f.w; ty = 3; }
    }
    const int lane = threadIdx.x & 31;
    const unsigned lt = (1u << lane) - 1u;
    #pragma unroll
    for (int t = 0; t < TTYPES; t++) {
        unsigned m = __ballot_sync(0xffffffffu, v && ty == t);
        if (m == 0u) continue;
        int leader = __ffs(m) - 1;
        int base = 0;
        if (lane == leader) base = atomicAdd(&g_counts[t], __popc(m));
        base = __shfl_sync(0xffffffffu, base, leader);
        if (v && ty == t) g_idx[t * BUCKET_CAP + base + __popc(m & lt)] = i;
    }
}

// ---------------- kernel 2: weight prep (transpose + split into K-halves) ---
__global__ void prep_weights(const float* __restrict__ W1, const float* __restrict__ W2) {
    int id = blockIdx.x * blockDim.x + threadIdx.x;
    if (id >= 20 * 128 * 16) return;
    const int tile = id >> 11;
    const int rem  = id & 2047;
    const int n    = rem >> 4;
    const int k0   = (rem & 15) * 8;
    const int half = k0 >> 6, kl = k0 & 63;
    const float* src;
    __nv_bfloat16 *dh, *dl;
    if (tile < 4) {
        src = W1 + (size_t)k0 * HID + tile * 128 + n;
        dh = g_w1t_hi + (tile * 2 + half) * WHALF_ELEM;
        dl = g_w1t_lo + (tile * 2 + half) * WHALF_ELEM;
    } else {
        const int tc = tile - 4;
        const int t = tc >> 2, c = tc & 3;
        src = W2 + (size_t)(c * 128 + k0) * HID + t * 128 + n;
        dh = g_w2t_hi + (tc * 2 + half) * WHALF_ELEM;
        dl = g_w2t_lo + (tc * 2 + half) * WHALF_ELEM;
    }
    uint32_t hw[4], lw[4];
    #pragma unroll
    for (int m = 0; m < 4; m++)
        pack2(src[(size_t)(2 * m) * HID], src[(size_t)(2 * m + 1) * HID], hw[m], lw[m]);
    const int e = n * 72 + kl;
    *(uint4*)((char*)dh + e * 2) = make_uint4(hw[0], hw[1], hw[2], hw[3]);
    *(uint4*)((char*)dl + e * 2) = make_uint4(lw[0], lw[1], lw[2], lw[3]);
}

// one GEMM half-phase: 4 k-steps of 16, 2(M)x4(N) mma tiles, 3-way bf16 split
__device__ __forceinline__ void gemm_half(
    float (*acc)[4][4],
    const uint32_t* __restrict__ Ah, const uint32_t* __restrict__ Al,
    const uint32_t* __restrict__ Bh, const uint32_t* __restrict__ Bl,
    int r0, int n0, int g, int t4, int kofs)
{
    #pragma unroll 1
    for (int ks = 0; ks < 4; ks++) {
        uint32_t ah[2][4], al[2][4];
        #pragma unroll
        for (int mt = 0; mt < 2; mt++) {
            const int ba = (r0 + mt * 16 + g) * TW + kofs + ks * 8 + t4;
            ah[mt][0]=Ah[ba];     ah[mt][1]=Ah[ba+8*TW];
            ah[mt][2]=Ah[ba+4];   ah[mt][3]=Ah[ba+8*TW+4];
            al[mt][0]=Al[ba];     al[mt][1]=Al[ba+8*TW];
            al[mt][2]=Al[ba+4];   al[mt][3]=Al[ba+8*TW+4];
        }
        uint32_t bh[4][2], bl[4][2];
        #pragma unroll
        for (int nt = 0; nt < 4; nt++) {
            const int bb = (n0 + nt * 8 + g) * WHALF_ROWW + ks * 8 + t4;
            bh[nt][0]=Bh[bb]; bh[nt][1]=Bh[bb+4];
            bl[nt][0]=Bl[bb]; bl[nt][1]=Bl[bb+4];
        }
        #pragma unroll
        for (int mt = 0; mt < 2; mt++)
            #pragma unroll
            for (int nt = 0; nt < 4; nt++) {
                mma_bf16(acc[mt][nt], ah[mt], bh[nt]);
                mma_bf16(acc[mt][nt], ah[mt], bl[nt]);
                mma_bf16(acc[mt][nt], al[mt], bh[nt]);
            }
    }
}

// ---------------- kernel 3: fused MLP, 512 threads, 4x4 warp grid ----------
__global__ __launch_bounds__(NTHREADS, 1)
void mlp_mma_kernel(const float* __restrict__ nf,
                    const float* __restrict__ b1,
                    const float* __restrict__ b2,
                    float* __restrict__ out,
                    int ntot)
{
    const int bty = blockIdx.x & 3;
    const int j   = blockIdx.x >> 2;
    const int cnt = g_counts[bty];
    if (j * MROWS >= cnt) return;

    extern __shared__ char smem[];
    int* gidx_s = (int*)(smem + SM_GIDX);
    uint32_t* Xh = (uint32_t*)(smem + SM_X_HI);
    uint32_t* Xl = (uint32_t*)(smem + SM_X_LO);
    uint32_t* Hh = (uint32_t*)(smem + SM_H_HI);
    uint32_t* Hl = (uint32_t*)(smem + SM_H_LO);
    const uint32_t sb = smem_u32(smem);

    const int tid = threadIdx.x;
    const int wid = tid >> 5, lid = tid & 31;
    const int g = lid >> 2, t4 = lid & 3;
    const int wm = wid >> 2, wn = wid & 3;   // 4(M) x 4(N) warps
    const int r0 = wm * 32;
    const int n0 = wn * 32;

    auto issue_stage = [&](int s) {
        const int c = s >> 2, t = s & 3;
        const __nv_bfloat16 *sh, *sl;
        if (t < 2) {
            sh = g_w1t_hi + (c * 2 + t) * WHALF_ELEM;
            sl = g_w1t_lo + (c * 2 + t) * WHALF_ELEM;
        } else {
            const int tc = bty * 4 + c;
            sh = g_w2t_hi + (tc * 2 + (t - 2)) * WHALF_ELEM;
            sl = g_w2t_lo + (tc * 2 + (t - 2)) * WHALF_ELEM;
        }
        const uint32_t dst = sb + SM_W0 + (uint32_t)(s & 1) * WBUF_B;
        for (int o = tid * 16; o < WHALF_B; o += NTHREADS * 16) {
            cpa16(dst + o,           (const char*)sh + o);
            cpa16(dst + WHALF_B + o, (const char*)sl + o);
        }
        CPA_COMMIT();
    };

    issue_stage(0);
    issue_stage(1);

    // ---- stage X: gather 128 rows, split; 4 threads/row, 32 cols each ----
    {
        const int row = tid >> 2, q4 = tid & 3;
        const int p = j * MROWS + row;
        const int gi = (p < cnt) ? g_idx[bty * BUCKET_CAP + p] : -1;
        if (q4 == 0) gidx_s[row] = gi;
        const float* src = nf + (size_t)(gi < 0 ? 0 : gi) * FIN + TTYPES + q4 * 32;
        #pragma unroll
        for (int q = 0; q < 4; q++) {
            float f[8];
            if (gi >= 0) {
                float4 f0 = *(const float4*)(src + q * 8);
                float4 f1 = *(const float4*)(src + q * 8 + 4);
                f[0]=f0.x; f[1]=f0.y; f[2]=f0.z; f[3]=f0.w;
                f[4]=f1.x; f[5]=f1.y; f[6]=f1.z; f[7]=f1.w;
            } else {
                #pragma unroll
                for (int m = 0; m < 8; m++) f[m] = 0.0f;
            }
            uint32_t hw[4], lw[4];
            #pragma unroll
            for (int m = 0; m < 4; m++) pack2(f[2*m], f[2*m+1], hw[m], lw[m]);
            const int w = row * TW + q4 * 16 + q * 4;
            *(uint4*)(Xh + w) = make_uint4(hw[0], hw[1], hw[2], hw[3]);
            *(uint4*)(Xl + w) = make_uint4(lw[0], lw[1], lw[2], lw[3]);
        }
    }
    CPA_WAIT(1);
    __syncthreads();

    float acc2[2][4][4];
    #pragma unroll
    for (int mt = 0; mt < 2; mt++)
        #pragma unroll
        for (int nt = 0; nt < 4; nt++)
            #pragma unroll
            for (int e = 0; e < 4; e++) acc2[mt][nt][e] = 0.0f;

    int s = 0;
    auto advance = [&]() {
        CPA_WAIT(0);
        __syncthreads();
        s++;
        if (s + 1 < 16) issue_stage(s + 1);
    };

    #pragma unroll 1
    for (int c = 0; c < 4; c++) {
        const uint32_t* B0h;
        const uint32_t* B0l;

        float acc1[2][4][4];
        #pragma unroll
        for (int mt = 0; mt < 2; mt++)
            #pragma unroll
            for (int nt = 0; nt < 4; nt++)
                #pragma unroll
                for (int e = 0; e < 4; e++) acc1[mt][nt][e] = 0.0f;

        // phase W1h0
        B0h = (const uint32_t*)(smem + SM_W0 + (s & 1) * WBUF_B);
        B0l = B0h + WHALF_B / 4;
        gemm_half(acc1, Xh, Xl, B0h, B0l, r0, n0, g, t4, 0);
        advance();

        // phase W1h1 + epilogue
        B0h = (const uint32_t*)(smem + SM_W0 + (s & 1) * WBUF_B);
        B0l = B0h + WHALF_B / 4;
        gemm_half(acc1, Xh, Xl, B0h, B0l, r0, n0, g, t4, 32);
        #pragma unroll
        for (int mt = 0; mt < 2; mt++)
            #pragma unroll
            for (int nt = 0; nt < 4; nt++) {
                const int jcol = c * 128 + n0 + nt * 8 + t4 * 2;
                const float2 bb = *(const float2*)(b1 + jcol);
                const int kw = wn * 16 + nt * 4 + t4;
                const int row0 = r0 + mt * 16 + g;
                float v0 = acc1[mt][nt][0] + bb.x;
                float v1 = acc1[mt][nt][1] + bb.y;
                float v2 = acc1[mt][nt][2] + bb.x;
                float v3 = acc1[mt][nt][3] + bb.y;
                float g0 = v0 * normcdff(v0), g1 = v1 * normcdff(v1);
                float g2 = v2 * normcdff(v2), g3 = v3 * normcdff(v3);
                uint32_t hi, lo;
                pack2(g0, g1, hi, lo);
                Hh[row0 * TW + kw] = hi;  Hl[row0 * TW + kw] = lo;
                pack2(g2, g3, hi, lo);
                Hh[(row0 + 8) * TW + kw] = hi;  Hl[(row0 + 8) * TW + kw] = lo;
            }
        advance();

        // phase W2h0
        B0h = (const uint32_t*)(smem + SM_W0 + (s & 1) * WBUF_B);
        B0l = B0h + WHALF_B / 4;
        gemm_half(acc2, Hh, Hl, B0h, B0l, r0, n0, g, t4, 0);
        advance();

        // phase W2h1
        B0h = (const uint32_t*)(smem + SM_W0 + (s & 1) * WBUF_B);
        B0l = B0h + WHALF_B / 4;
        gemm_half(acc2, Hh, Hl, B0h, B0l, r0, n0, g, t4, 32);
        advance();
    }

    // ---- final: bias + scatter store ----
    #pragma unroll
    for (int mt = 0; mt < 2; mt++)
        #pragma unroll
        for (int nt = 0; nt < 4; nt++) {
            const int jcol = n0 + nt * 8 + t4 * 2;
            const float2 bb = *(const float2*)(b2 + bty * 128 + jcol);
            const int row0 = r0 + mt * 16 + g;
            const int gi0 = gidx_s[row0];
            const int gi1 = gidx_s[row0 + 8];
            if (gi0 >= 0) {
                float2 o = make_float2(acc2[mt][nt][0] + bb.x, acc2[mt][nt][1] + bb.y);
                *(float2*)(out + (size_t)gi0 * D_OUT + jcol) = o;
            }
            if (gi1 >= 0) {
                float2 o = make_float2(acc2[mt][nt][2] + bb.x, acc2[mt][nt][3] + bb.y);
                *(float2*)(out + (size_t)gi1 * D_OUT + jcol) = o;
            }
        }
}

// ---------------- host launcher ----------------
extern "C" void kernel_launch(void* const* d_in, const int* in_sizes, int n_in,
                              void* d_out, int out_size)
{
    const float* nf = (const float*)d_in[0];
    const float* W1 = (const float*)d_in[1];
    const float* b1 = (const float*)d_in[2];
    const float* W2 = (const float*)d_in[3];
    const float* b2 = (const float*)d_in[4];
    float* out = (float*)d_out;

    const int ntot   = in_sizes[0] / FIN;
    const int ntiles = (ntot + MROWS - 1) / MROWS;

    cudaFuncSetAttribute(mlp_mma_kernel,
                         cudaFuncAttributeMaxDynamicSharedMemorySize, SM_TOTAL);

    zero_kernel<<<1, 32>>>();
    bucket_kernel<<<(ntot + 255) / 256, 256>>>(nf, ntot);
    prep_weights<<<(20 * 128 * 16 + 255) / 256, 256>>>(W1, W2);
    mlp_mma_kernel<<<4 * ntiles, NTHREADS, SM_TOTAL>>>(nf, b1, b2, out, ntot);
}

// round 13
// speedup vs baseline: 1.0319x; 1.0319x over previous
#include <cuda_runtime.h>
#include <cuda_bf16.h>
#include <stdint.h>

#define TTYPES   4
#define D_OUT    128
#define FIN      132
#define HID      512
#define MROWS    128
#define NTHREADS 512
#define BUCKET_CAP 262144

#define TW        68            // X/H row stride in words (136 bf16 = 128+8 pad)
#define XROW_B    272           // X/H row stride in bytes
#define XH_B      34816         // one X or H buffer (hi or lo)

#define WHALF_ROWW 36           // W half-tile row stride in words (72 bf16)
#define WROW_B     144
#define WHALF_ELEM 9216         // 128 * 72 bf16
#define WHALF_B    18432
#define WBUF_B     36864        // hi + lo

// ---------------- device scratch (static: allocation-free) ----------------
__device__ __nv_bfloat16 g_w1t_hi[4 * 2 * WHALF_ELEM];
__device__ __nv_bfloat16 g_w1t_lo[4 * 2 * WHALF_ELEM];
__device__ __nv_bfloat16 g_w2t_hi[16 * 2 * WHALF_ELEM];
__device__ __nv_bfloat16 g_w2t_lo[16 * 2 * WHALF_ELEM];
__device__ int g_counts[TTYPES];
__device__ int g_idx[TTYPES * BUCKET_CAP];

// ---------------- smem layout (bytes) ----------------
#define SM_GIDX  0
#define SM_X_HI  512
#define SM_X_LO  (SM_X_HI + XH_B)
#define SM_W0    (SM_X_LO + XH_B)
#define SM_W1    (SM_W0 + WBUF_B)
#define SM_H_HI  (SM_W1 + WBUF_B)
#define SM_H_LO  (SM_H_HI + XH_B)
#define SM_TOTAL (SM_H_LO + XH_B)        // 213504 B < 227 KB cap

// ---------------- helpers ----------------
__device__ __forceinline__ void mma_bf16(float* c, const uint32_t* a, const uint32_t* b) {
    asm volatile(
        "mma.sync.aligned.m16n8k16.row.col.f32.bf16.bf16.f32 "
        "{%0,%1,%2,%3}, {%4,%5,%6,%7}, {%8,%9}, {%0,%1,%2,%3};"
        : "+f"(c[0]), "+f"(c[1]), "+f"(c[2]), "+f"(c[3])
        : "r"(a[0]), "r"(a[1]), "r"(a[2]), "r"(a[3]), "r"(b[0]), "r"(b[1]));
}
__device__ __forceinline__ void ldm4(uint32_t* r, uint32_t addr) {
    asm volatile("ldmatrix.sync.aligned.m8n8.x4.shared.b16 {%0,%1,%2,%3}, [%4];"
        : "=r"(r[0]), "=r"(r[1]), "=r"(r[2]), "=r"(r[3]) : "r"(addr));
}
__device__ __forceinline__ uint32_t smem_u32(const void* p) {
    uint32_t a;
    asm("{ .reg .u64 t; cvta.to.shared.u64 t, %1; cvt.u32.u64 %0, t; }"
        : "=r"(a) : "l"(p));
    return a;
}
__device__ __forceinline__ void cpa16(uint32_t s, const void* g) {
    asm volatile("cp.async.cg.shared.global [%0], [%1], 16;" :: "r"(s), "l"(g));
}
#define CPA_COMMIT() asm volatile("cp.async.commit_group;" ::: "memory")
#define CPA_WAIT(n)  asm volatile("cp.async.wait_group %0;" :: "n"(n) : "memory")

__device__ __forceinline__ void split_bf16(float v, unsigned short& h, unsigned short& l) {
    __nv_bfloat16 hb = __float2bfloat16(v);
    h = __bfloat16_as_ushort(hb);
    l = __bfloat16_as_ushort(__float2bfloat16(v - __bfloat162float(hb)));
}
__device__ __forceinline__ void pack2(float a, float b, uint32_t& hi, uint32_t& lo) {
    unsigned short ha, la, hb, lb;
    split_bf16(a, ha, la); split_bf16(b, hb, lb);
    hi = (uint32_t)ha | ((uint32_t)hb << 16);
    lo = (uint32_t)la | ((uint32_t)lb << 16);
}

// ---------------- kernel 0 / 1: counters + bucketing ----------------
__global__ void zero_kernel() {
    if (threadIdx.x < TTYPES) g_counts[threadIdx.x] = 0;
}
__global__ void bucket_kernel(const float* __restrict__ nf, int ntot) {
    int i = blockIdx.x * blockDim.x + threadIdx.x;
    bool v = i < ntot;
    int ty = 0;
    if (v) {
        float4 f = *(const float4*)(nf + (size_t)i * FIN);
        float m = f.x;
        if (f.y > m) { m = f.y; ty = 1; }
        if (f.z > m) { m = f.z; ty = 2; }
        if (f.w > m) { m = f.w; ty = 3; }
    }
    const int lane = threadIdx.x & 31;
    const unsigned lt = (1u << lane) - 1u;
    #pragma unroll
    for (int t = 0; t < TTYPES; t++) {
        unsigned m = __ballot_sync(0xffffffffu, v && ty == t);
        if (m == 0u) continue;
        int leader = __ffs(m) - 1;
        int base = 0;
        if (lane == leader) base = atomicAdd(&g_counts[t], __popc(m));
        base = __shfl_sync(0xffffffffu, base, leader);
        if (v && ty == t) g_idx[t * BUCKET_CAP + base + __popc(m & lt)] = i;
    }
}

// ---------------- kernel 2: weight prep (transpose + split into K-halves) ---
__global__ void prep_weights(const float* __restrict__ W1, const float* __restrict__ W2) {
    int id = blockIdx.x * blockDim.x + threadIdx.x;
    if (id >= 20 * 128 * 16) return;
    const int tile = id >> 11;
    const int rem  = id & 2047;
    const int n    = rem >> 4;
    const int k0   = (rem & 15) * 8;
    const int half = k0 >> 6, kl = k0 & 63;
    const float* src;
    __nv_bfloat16 *dh, *dl;
    if (tile < 4) {
        src = W1 + (size_t)k0 * HID + tile * 128 + n;
        dh = g_w1t_hi + (tile * 2 + half) * WHALF_ELEM;
        dl = g_w1t_lo + (tile * 2 + half) * WHALF_ELEM;
    } else {
        const int tc = tile - 4;
        const int t = tc >> 2, c = tc & 3;
        src = W2 + (size_t)(c * 128 + k0) * HID + t * 128 + n;
        dh = g_w2t_hi + (tc * 2 + half) * WHALF_ELEM;
        dl = g_w2t_lo + (tc * 2 + half) * WHALF_ELEM;
    }
    uint32_t hw[4], lw[4];
    #pragma unroll
    for (int m = 0; m < 4; m++)
        pack2(src[(size_t)(2 * m) * HID], src[(size_t)(2 * m + 1) * HID], hw[m], lw[m]);
    const int e = n * 72 + kl;
    *(uint4*)((char*)dh + e * 2) = make_uint4(hw[0], hw[1], hw[2], hw[3]);
    *(uint4*)((char*)dl + e * 2) = make_uint4(lw[0], lw[1], lw[2], lw[3]);
}

// one GEMM half-phase via ldmatrix: 4 k-steps of 16, 2(M)x4(N) tiles, 3x split.
// aHi/aLo: lane-resolved smem addr of A mt=0 fragment at ks=0 (hi/lo buffers).
// bHi/bLo: lane-resolved addr of B nt-pair 0 at ks=0.
__device__ __forceinline__ void gemm_half(
    float (*acc)[4][4],
    uint32_t aHi, uint32_t aLo, uint32_t bHi, uint32_t bLo)
{
    #pragma unroll 1
    for (int ks = 0; ks < 4; ks++) {
        uint32_t ah[2][4], al[2][4], bh[2][4], bl[2][4];
        ldm4(ah[0], aHi + ks * 32);
        ldm4(ah[1], aHi + 16 * XROW_B + ks * 32);
        ldm4(al[0], aLo + ks * 32);
        ldm4(al[1], aLo + 16 * XROW_B + ks * 32);
        ldm4(bh[0], bHi + ks * 32);
        ldm4(bh[1], bHi + 16 * WROW_B + ks * 32);
        ldm4(bl[0], bLo + ks * 32);
        ldm4(bl[1], bLo + 16 * WROW_B + ks * 32);
        // bh[p] = {b0(nt=2p), b1(nt=2p), b0(nt=2p+1), b1(nt=2p+1)}
        #pragma unroll
        for (int mt = 0; mt < 2; mt++)
            #pragma unroll
            for (int nt = 0; nt < 4; nt++) {
                const uint32_t* Bh = &bh[nt >> 1][(nt & 1) * 2];
                const uint32_t* Bl = &bl[nt >> 1][(nt & 1) * 2];
                mma_bf16(acc[mt][nt], ah[mt], Bh);
                mma_bf16(acc[mt][nt], ah[mt], Bl);
                mma_bf16(acc[mt][nt], al[mt], Bh);
            }
    }
}

// ---------------- kernel 3: fused MLP, 512 threads, 4x4 warp grid ----------
__global__ __launch_bounds__(NTHREADS, 1)
void mlp_mma_kernel(const float* __restrict__ nf,
                    const float* __restrict__ b1,
                    const float* __restrict__ b2,
                    float* __restrict__ out,
                    int ntot)
{
    const int bty = blockIdx.x & 3;
    const int j   = blockIdx.x >> 2;
    const int cnt = g_counts[bty];
    if (j * MROWS >= cnt) return;

    extern __shared__ char smem[];
    int* gidx_s = (int*)(smem + SM_GIDX);
    uint32_t* Xh = (uint32_t*)(smem + SM_X_HI);
    uint32_t* Xl = (uint32_t*)(smem + SM_X_LO);
    uint32_t* Hh = (uint32_t*)(smem + SM_H_HI);
    uint32_t* Hl = (uint32_t*)(smem + SM_H_LO);
    const uint32_t sb = smem_u32(smem);

    const int tid = threadIdx.x;
    const int wid = tid >> 5, lid = tid & 31;
    const int g = lid >> 2, t4 = lid & 3;
    const int wm = wid >> 2, wn = wid & 3;   // 4(M) x 4(N) warps
    const int r0 = wm * 32;
    const int n0 = wn * 32;

    // ldmatrix lane address components
    const int a_m  = (lid & 7) + (((lid >> 3) & 1) << 3);  // A: groups 0-7/8-15 rows, 16+: k+8
    const int a_kB = (((lid >> 4) & 1) << 4);              // +16B (8 bf16)
    const int b_n  = (lid & 7) + (((lid >> 4) & 1) << 3);  // B: 16+ -> nt+1
    const int b_kB = (((lid >> 3) & 1) << 4);

    const uint32_t xA_hi = sb + SM_X_HI + (r0 + a_m) * XROW_B + a_kB;
    const uint32_t xA_lo = xA_hi + XH_B;
    const uint32_t hA_hi = sb + SM_H_HI + (r0 + a_m) * XROW_B + a_kB;
    const uint32_t hA_lo = hA_hi + XH_B;
    const uint32_t bOff  = (uint32_t)((n0 + b_n) * WROW_B + b_kB);

    auto issue_stage = [&](int s) {
        const int c = s >> 2, t = s & 3;
        const __nv_bfloat16 *sh, *sl;
        if (t < 2) {
            sh = g_w1t_hi + (c * 2 + t) * WHALF_ELEM;
            sl = g_w1t_lo + (c * 2 + t) * WHALF_ELEM;
        } else {
            const int tc = bty * 4 + c;
            sh = g_w2t_hi + (tc * 2 + (t - 2)) * WHALF_ELEM;
            sl = g_w2t_lo + (tc * 2 + (t - 2)) * WHALF_ELEM;
        }
        const uint32_t dst = sb + SM_W0 + (uint32_t)(s & 1) * WBUF_B;
        for (int o = tid * 16; o < WHALF_B; o += NTHREADS * 16) {
            cpa16(dst + o,           (const char*)sh + o);
            cpa16(dst + WHALF_B + o, (const char*)sl + o);
        }
        CPA_COMMIT();
    };

    issue_stage(0);
    issue_stage(1);

    // ---- stage X: gather 128 rows, split; 4 threads/row, 32 cols each ----
    {
        const int row = tid >> 2, q4 = tid & 3;
        const int p = j * MROWS + row;
        const int gi = (p < cnt) ? g_idx[bty * BUCKET_CAP + p] : -1;
        if (q4 == 0) gidx_s[row] = gi;
        const float* src = nf + (size_t)(gi < 0 ? 0 : gi) * FIN + TTYPES + q4 * 32;
        #pragma unroll
        for (int q = 0; q < 4; q++) {
            float f[8];
            if (gi >= 0) {
                float4 f0 = *(const float4*)(src + q * 8);
                float4 f1 = *(const float4*)(src + q * 8 + 4);
                f[0]=f0.x; f[1]=f0.y; f[2]=f0.z; f[3]=f0.w;
                f[4]=f1.x; f[5]=f1.y; f[6]=f1.z; f[7]=f1.w;
            } else {
                #pragma unroll
                for (int m = 0; m < 8; m++) f[m] = 0.0f;
            }
            uint32_t hw[4], lw[4];
            #pragma unroll
            for (int m = 0; m < 4; m++) pack2(f[2*m], f[2*m+1], hw[m], lw[m]);
            const int w = row * TW + q4 * 16 + q * 4;
            *(uint4*)(Xh + w) = make_uint4(hw[0], hw[1], hw[2], hw[3]);
            *(uint4*)(Xl + w) = make_uint4(lw[0], lw[1], lw[2], lw[3]);
        }
    }
    CPA_WAIT(1);
    __syncthreads();

    float acc2[2][4][4];
    #pragma unroll
    for (int mt = 0; mt < 2; mt++)
        #pragma unroll
        for (int nt = 0; nt < 4; nt++)
            #pragma unroll
            for (int e = 0; e < 4; e++) acc2[mt][nt][e] = 0.0f;

    int s = 0;
    auto advance = [&]() {
        CPA_WAIT(0);
        __syncthreads();
        s++;
        if (s + 1 < 16) issue_stage(s + 1);
    };
    auto wbufB = [&]() -> uint32_t {
        return sb + SM_W0 + (uint32_t)(s & 1) * WBUF_B + bOff;
    };

    #pragma unroll 1
    for (int c = 0; c < 4; c++) {
        float acc1[2][4][4];
        #pragma unroll
        for (int mt = 0; mt < 2; mt++)
            #pragma unroll
            for (int nt = 0; nt < 4; nt++)
                #pragma unroll
                for (int e = 0; e < 4; e++) acc1[mt][nt][e] = 0.0f;

        // phase W1h0 (X k 0..63)
        { uint32_t b = wbufB(); gemm_half(acc1, xA_hi, xA_lo, b, b + WHALF_B); }
        advance();

        // phase W1h1 (X k 64..127) + epilogue
        { uint32_t b = wbufB(); gemm_half(acc1, xA_hi + 128, xA_lo + 128, b, b + WHALF_B); }
        #pragma unroll
        for (int mt = 0; mt < 2; mt++)
            #pragma unroll
            for (int nt = 0; nt < 4; nt++) {
                const int jcol = c * 128 + n0 + nt * 8 + t4 * 2;
                const float2 bb = *(const float2*)(b1 + jcol);
                const int kw = wn * 16 + nt * 4 + t4;
                const int row0 = r0 + mt * 16 + g;
                float v0 = acc1[mt][nt][0] + bb.x;
                float v1 = acc1[mt][nt][1] + bb.y;
                float v2 = acc1[mt][nt][2] + bb.x;
                float v3 = acc1[mt][nt][3] + bb.y;
                float g0 = v0 * normcdff(v0), g1 = v1 * normcdff(v1);
                float g2 = v2 * normcdff(v2), g3 = v3 * normcdff(v3);
                uint32_t hi, lo;
                pack2(g0, g1, hi, lo);
                Hh[row0 * TW + kw] = hi;  Hl[row0 * TW + kw] = lo;
                pack2(g2, g3, hi, lo);
                Hh[(row0 + 8) * TW + kw] = hi;  Hl[(row0 + 8) * TW + kw] = lo;
            }
        advance();

        // phase W2h0 (H k 0..63)
        { uint32_t b = wbufB(); gemm_half(acc2, hA_hi, hA_lo, b, b + WHALF_B); }
        advance();

        // phase W2h1 (H k 64..127)
        { uint32_t b = wbufB(); gemm_half(acc2, hA_hi + 128, hA_lo + 128, b, b + WHALF_B); }
        advance();
    }

    // ---- final: bias + scatter store ----
    #pragma unroll
    for (int mt = 0; mt < 2; mt++)
        #pragma unroll
        for (int nt = 0; nt < 4; nt++) {
            const int jcol = n0 + nt * 8 + t4 * 2;
            const float2 bb = *(const float2*)(b2 + bty * 128 + jcol);
            const int row0 = r0 + mt * 16 + g;
            const int gi0 = gidx_s[row0];
            const int gi1 = gidx_s[row0 + 8];
            if (gi0 >= 0) {
                float2 o = make_float2(acc2[mt][nt][0] + bb.x, acc2[mt][nt][1] + bb.y);
                *(float2*)(out + (size_t)gi0 * D_OUT + jcol) = o;
            }
            if (gi1 >= 0) {
                float2 o = make_float2(acc2[mt][nt][2] + bb.x, acc2[mt][nt][3] + bb.y);
                *(float2*)(out + (size_t)gi1 * D_OUT + jcol) = o;
            }
        }
}

// ---------------- host launcher ----------------
extern "C" void kernel_launch(void* const* d_in, const int* in_sizes, int n_in,
                              void* d_out, int out_size)
{
    const float* nf = (const float*)d_in[0];
    const float* W1 = (const float*)d_in[1];
    const float* b1 = (const float*)d_in[2];
    const float* W2 = (const float*)d_in[3];
    const float* b2 = (const float*)d_in[4];
    float* out = (float*)d_out;

    const int ntot   = in_sizes[0] / FIN;
    const int ntiles = (ntot + MROWS - 1) / MROWS;

    cudaFuncSetAttribute(mlp_mma_kernel,
                         cudaFuncAttributeMaxDynamicSharedMemorySize, SM_TOTAL);

    zero_kernel<<<1, 32>>>();
    bucket_kernel<<<(ntot + 255) / 256, 256>>>(nf, ntot);
    prep_weights<<<(20 * 128 * 16 + 255) / 256, 256>>>(W1, W2);
    mlp_mma_kernel<<<4 * ntiles, NTHREADS, SM_TOTAL>>>(nf, b1, b2, out, ntot);
}